// round 7
// baseline (speedup 1.0000x reference)
#include <cuda_runtime.h>
#include <cstdint>

#define NTHREADS   256
#define TILE_BOXES 512              // boxes per tile (8 KB per array per stage)
#define STAGES     2
#define GRID_BLOCKS (148 * 8)
#define MAX_BLOCKS  4096

__device__ float2 g_part[MAX_BLOCKS];
__device__ unsigned int g_count;    // atomicInc wraps -> self-resetting

__device__ __forceinline__ uint32_t smem_u32(const void* p) {
    uint32_t a;
    asm("{ .reg .u64 t; cvta.to.shared.u64 t, %1; cvt.u32.u64 %0, t; }"
        : "=r"(a) : "l"(p));
    return a;
}
__device__ __forceinline__ void mbar_init(uint32_t a, uint32_t cnt) {
    asm volatile("mbarrier.init.shared.b64 [%0], %1;" :: "r"(a), "r"(cnt) : "memory");
}
__device__ __forceinline__ void mbar_expect_tx(uint32_t a, uint32_t bytes) {
    asm volatile("mbarrier.arrive.expect_tx.shared.b64 _, [%0], %1;"
                 :: "r"(a), "r"(bytes) : "memory");
}
__device__ __forceinline__ void bulk_g2s(uint32_t dst, const void* src,
                                         uint32_t bytes, uint32_t mbar) {
    asm volatile(
        "cp.async.bulk.shared::cluster.global.mbarrier::complete_tx::bytes "
        "[%0], [%1], %2, [%3];"
        :: "r"(dst), "l"(src), "r"(bytes), "r"(mbar) : "memory");
}
__device__ __forceinline__ void mbar_wait(uint32_t a, uint32_t ph) {
    asm volatile(
        "{\n\t"
        ".reg .pred P;\n\t"
        "LW%=:\n\t"
        "mbarrier.try_wait.parity.acquire.cta.shared::cta.b64 P, [%0], %1, 0x989680;\n\t"
        "@P bra LD%=;\n\t"
        "bra LW%=;\n\t"
        "LD%=:\n\t"
        "}" :: "r"(a), "r"(ph) : "memory");
}

__device__ __forceinline__ void iou_accum(const float4 p, const float4 t,
                                          float& lsum, float& lcnt) {
    float phw = p.z * 0.5f, phh = p.w * 0.5f;
    float thw = t.z * 0.5f, thh = t.w * 0.5f;

    float ix = fminf(p.x + phw, t.x + thw) - fmaxf(p.x - phw, t.x - thw);
    float iy = fminf(p.y + phh, t.y + thh) - fmaxf(p.y - phh, t.y - thh);
    float inter = fmaxf(ix, 0.0f) * fmaxf(iy, 0.0f);

    float area_p = p.z * p.w;          // nonneg for valid boxes
    float area_t = t.z * t.w;
    float iou = inter / (area_p + area_t - inter + 1e-6f);

    bool valid = !(t.z == -1.0f && t.w == -1.0f);  // sentinel is [-1]*4
    if (valid) { lsum += iou; lcnt += 1.0f; }
}

__global__ void __launch_bounds__(NTHREADS)
iou_tma_kernel(const float4* __restrict__ pred,
               const float4* __restrict__ truth,
               int n, int ntiles,
               float* __restrict__ out, int out_size) {
    __shared__ __align__(128) float4 sp[STAGES][TILE_BOXES];
    __shared__ __align__(128) float4 st[STAGES][TILE_BOXES];
    __shared__ __align__(8) unsigned long long mbar[STAGES];

    const int tid = threadIdx.x;

    uint32_t mb[STAGES], spa[STAGES], sta[STAGES];
    #pragma unroll
    for (int s = 0; s < STAGES; s++) {
        mb[s]  = smem_u32(&mbar[s]);
        spa[s] = smem_u32(&sp[s][0]);
        sta[s] = smem_u32(&st[s][0]);
    }

    if (tid == 0) {
        #pragma unroll
        for (int s = 0; s < STAGES; s++) mbar_init(mb[s], 1);
        // make inits visible to the async proxy before first bulk copy
        asm volatile("fence.proxy.async.shared::cta;" ::: "memory");
    }
    __syncthreads();

    // number of tiles this CTA owns: tiles blockIdx.x + k*gridDim.x < ntiles
    int m = (ntiles - blockIdx.x + gridDim.x - 1) / gridDim.x;
    if (m < 0) m = 0;

    // prologue: issue first STAGES tiles
    if (tid == 0) {
        #pragma unroll
        for (int s = 0; s < STAGES; s++) {
            if (s < m) {
                int t = blockIdx.x + s * gridDim.x;
                int base = t * TILE_BOXES;
                int cnt = n - base; if (cnt > TILE_BOXES) cnt = TILE_BOXES;
                uint32_t bytes = (uint32_t)cnt * 16u;
                mbar_expect_tx(mb[s], 2u * bytes);
                bulk_g2s(spa[s], pred + base, bytes, mb[s]);
                bulk_g2s(sta[s], truth + base, bytes, mb[s]);
            }
        }
    }

    float lsum = 0.0f, lcnt = 0.0f;
    uint32_t ph[STAGES] = {0, 0};

    for (int k = 0; k < m; k++) {
        int s = k % STAGES;
        int t = blockIdx.x + k * gridDim.x;
        int base = t * TILE_BOXES;
        int cnt = n - base; if (cnt > TILE_BOXES) cnt = TILE_BOXES;

        mbar_wait(mb[s], ph[s]);
        ph[s] ^= 1;

        for (int idx = tid; idx < cnt; idx += NTHREADS) {
            float4 p = sp[s][idx];
            float4 tt = st[s][idx];
            iou_accum(p, tt, lsum, lcnt);
        }
        __syncthreads();   // stage fully consumed before refill

        if (tid == 0) {
            int kn = k + STAGES;
            if (kn < m) {
                int tn = blockIdx.x + kn * gridDim.x;
                int bn = tn * TILE_BOXES;
                int cn = n - bn; if (cn > TILE_BOXES) cn = TILE_BOXES;
                uint32_t bytes = (uint32_t)cn * 16u;
                mbar_expect_tx(mb[s], 2u * bytes);
                bulk_g2s(spa[s], pred + bn, bytes, mb[s]);
                bulk_g2s(sta[s], truth + bn, bytes, mb[s]);
            }
        }
    }

    // ---- block reduce (fp32) ----
    #pragma unroll
    for (int off = 16; off > 0; off >>= 1) {
        lsum += __shfl_down_sync(0xffffffffu, lsum, off);
        lcnt += __shfl_down_sync(0xffffffffu, lcnt, off);
    }
    __shared__ float ssum[NTHREADS / 32];
    __shared__ float scnt[NTHREADS / 32];
    int warp = tid >> 5, lane = tid & 31;
    if (lane == 0) { ssum[warp] = lsum; scnt[warp] = lcnt; }
    __syncthreads();

    __shared__ bool is_last;
    if (tid == 0) {
        float bsum = 0.0f, bcnt = 0.0f;
        #pragma unroll
        for (int w = 0; w < NTHREADS / 32; w++) { bsum += ssum[w]; bcnt += scnt[w]; }
        g_part[blockIdx.x] = make_float2(bsum, bcnt);
        __threadfence();
        unsigned int old = atomicInc(&g_count, gridDim.x - 1);
        is_last = (old == gridDim.x - 1);
    }
    __syncthreads();

    if (is_last) {
        double dsum = 0.0, dcnt = 0.0;
        for (int b = tid; b < gridDim.x; b += NTHREADS) {
            float2 v = g_part[b];
            dsum += (double)v.x;
            dcnt += (double)v.y;
        }
        #pragma unroll
        for (int off = 16; off > 0; off >>= 1) {
            dsum += __shfl_down_sync(0xffffffffu, dsum, off);
            dcnt += __shfl_down_sync(0xffffffffu, dcnt, off);
        }
        __shared__ double dssum[NTHREADS / 32];
        __shared__ double dscnt[NTHREADS / 32];
        if (lane == 0) { dssum[warp] = dsum; dscnt[warp] = dcnt; }
        __syncthreads();
        if (tid == 0) {
            double fsum = 0.0, fcnt = 0.0;
            #pragma unroll
            for (int w = 0; w < NTHREADS / 32; w++) { fsum += dssum[w]; fcnt += dscnt[w]; }
            float mval = (fcnt > 0.0)
                           ? (float)(fsum / (fcnt < 1.0 ? 1.0 : fcnt))
                           : 0.0f;
            for (int i = 0; i < out_size; i++) out[i] = mval;
        }
    }
}

extern "C" void kernel_launch(void* const* d_in, const int* in_sizes, int n_in,
                              void* d_out, int out_size) {
    const float4* pred  = (const float4*)d_in[0];
    const float4* truth = (const float4*)d_in[1];
    int n = in_sizes[0] / 4;                      // boxes
    int ntiles = (n + TILE_BOXES - 1) / TILE_BOXES;

    int blocks = GRID_BLOCKS;
    if (blocks > ntiles) blocks = ntiles;
    if (blocks > MAX_BLOCKS) blocks = MAX_BLOCKS;

    iou_tma_kernel<<<blocks, NTHREADS>>>(pred, truth, n, ntiles,
                                         (float*)d_out, out_size);
}

// round 8
// speedup vs baseline: 1.2330x; 1.2330x over previous
#include <cuda_runtime.h>

#define NTHREADS 256
#define GRID_BLOCKS (148 * 16)

// Zero-initialized device accumulators. The finalize kernel resets them after
// reading, so every graph replay starts from zero — no init kernel needed.
__device__ double g_iou_sum;
__device__ double g_valid_cnt;

__global__ void __launch_bounds__(NTHREADS)
iou_reduce_kernel(const float4* __restrict__ pred,
                  const float4* __restrict__ truth,
                  int n) {
    float lsum = 0.0f;
    float lcnt = 0.0f;

    int idx = blockIdx.x * NTHREADS + threadIdx.x;
    int stride = gridDim.x * NTHREADS;

    // Natural grid-stride loop, __ldg float4 — R1's fastest-measured mainloop.
    for (int i = idx; i < n; i += stride) {
        float4 p = __ldg(pred + i);
        float4 t = __ldg(truth + i);

        float phw = p.z * 0.5f, phh = p.w * 0.5f;
        float thw = t.z * 0.5f, thh = t.w * 0.5f;

        float ix = fminf(p.x + phw, t.x + thw) - fmaxf(p.x - phw, t.x - thw);
        float iy = fminf(p.y + phh, t.y + thh) - fmaxf(p.y - phh, t.y - thh);
        float inter = fmaxf(ix, 0.0f) * fmaxf(iy, 0.0f);

        float area_p = p.z * p.w;      // valid boxes have w,h >= 0
        float area_t = t.z * t.w;
        float iou = inter / (area_p + area_t - inter + 1e-6f);

        bool valid = !(t.z == -1.0f && t.w == -1.0f);  // sentinel [-1]*4
        if (valid) {
            lsum += iou;
            lcnt += 1.0f;
        }
    }

    // Warp reduce
    #pragma unroll
    for (int off = 16; off > 0; off >>= 1) {
        lsum += __shfl_down_sync(0xffffffffu, lsum, off);
        lcnt += __shfl_down_sync(0xffffffffu, lcnt, off);
    }

    __shared__ float ssum[NTHREADS / 32];
    __shared__ float scnt[NTHREADS / 32];
    int warp = threadIdx.x >> 5;
    int lane = threadIdx.x & 31;
    if (lane == 0) {
        ssum[warp] = lsum;
        scnt[warp] = lcnt;
    }
    __syncthreads();

    if (warp == 0) {
        float bsum = (lane < NTHREADS / 32) ? ssum[lane] : 0.0f;
        float bcnt = (lane < NTHREADS / 32) ? scnt[lane] : 0.0f;
        #pragma unroll
        for (int off = 4; off > 0; off >>= 1) {
            bsum += __shfl_down_sync(0xffffffffu, bsum, off);
            bcnt += __shfl_down_sync(0xffffffffu, bcnt, off);
        }
        if (lane == 0) {
            atomicAdd(&g_iou_sum, (double)bsum);
            atomicAdd(&g_valid_cnt, (double)bcnt);
        }
    }
}

// Reads the accumulators, writes the result, then resets them for the next
// graph replay (deferred reset instead of an init kernel).
__global__ void iou_finalize_kernel(float* __restrict__ out, int out_size) {
    if (threadIdx.x == 0) {
        double s = g_iou_sum;
        double c = g_valid_cnt;
        float m = (c > 0.0) ? (float)(s / (c < 1.0 ? 1.0 : c)) : 0.0f;
        for (int i = 0; i < out_size; i++) out[i] = m;
        g_iou_sum = 0.0;
        g_valid_cnt = 0.0;
    }
}

extern "C" void kernel_launch(void* const* d_in, const int* in_sizes, int n_in,
                              void* d_out, int out_size) {
    const float4* pred  = (const float4*)d_in[0];
    const float4* truth = (const float4*)d_in[1];
    int n = in_sizes[0] / 4;   // number of boxes (float4 elements)

    int blocks = GRID_BLOCKS;
    int needed = (n + NTHREADS - 1) / NTHREADS;
    if (blocks > needed) blocks = needed;

    iou_reduce_kernel<<<blocks, NTHREADS>>>(pred, truth, n);
    iou_finalize_kernel<<<1, 32>>>((float*)d_out, out_size);
}